// round 1
// baseline (speedup 1.0000x reference)
#include <cuda_runtime.h>
#include <math.h>

#define D 256
#define TT 4096
#define NB 4
#define BT (NB*TT)      // 16384 rows
#define KSTR 257        // padded K smem stride (2-way conflict max)

// -------- scratch (allocation-free: __device__ globals) --------
__device__ float g_xn[BT * D];
__device__ float g_q[BT * D];
__device__ float g_k[BT * D];
__device__ float g_v[BT * D];
__device__ float g_attn[BT * D];
__device__ float g_hn[BT * D];
__device__ float g_h[BT * 4 * D];

// ---------------- RMSNorm: one block per row ----------------
__global__ void rmsnorm_kernel(const float* __restrict__ x,
                               const float* __restrict__ w,
                               float* __restrict__ out) {
    int row = blockIdx.x;
    int t = threadIdx.x;                 // 256 threads, D=256
    float v = x[(size_t)row * D + t];
    float ss = v * v;
    #pragma unroll
    for (int o = 16; o > 0; o >>= 1) ss += __shfl_xor_sync(0xffffffffu, ss, o);
    __shared__ float ws[8];
    if ((t & 31) == 0) ws[t >> 5] = ss;
    __syncthreads();
    float tot = 0.f;
    #pragma unroll
    for (int i = 0; i < 8; i++) tot += ws[i];
    float r = rsqrtf(tot * (1.0f / D) + 1e-6f);
    out[(size_t)row * D + t] = v * r * w[t];
}

// ---------------- tiled SGEMM: C[M,N] = A[M,K] @ W[N,K]^T + bias (+epilogue) ---
// EPI: 0 = bias, 1 = bias+GELU(exact), 2 = bias+residual
__device__ __forceinline__ float gelu_exact(float x) {
    return 0.5f * x * (1.0f + erff(x * 0.70710678118654752440f));
}

template <int EPI>
__global__ void __launch_bounds__(256)
gemm_kernel(const float* __restrict__ A, const float* __restrict__ W,
            const float* __restrict__ bias, const float* __restrict__ res,
            float* __restrict__ C, int M, int N, int K) {
    __shared__ __align__(16) float As[8][128];
    __shared__ __align__(16) float Bs[8][128];

    int tid = threadIdx.x;
    int tx = tid & 15, ty = tid >> 4;
    int lr = tid >> 1, lk = (tid & 1) * 4;

    const float* Ap = A + (size_t)(blockIdx.y * 128 + lr) * K + lk;
    const float* Wp = W + (size_t)(blockIdx.x * 128 + lr) * K + lk;

    float acc[8][8];
    #pragma unroll
    for (int i = 0; i < 8; i++)
        #pragma unroll
        for (int j = 0; j < 8; j++) acc[i][j] = 0.f;

    for (int kt = 0; kt < K; kt += 8) {
        float4 a = *(const float4*)Ap;
        float4 b = *(const float4*)Wp;
        As[lk + 0][lr] = a.x; As[lk + 1][lr] = a.y;
        As[lk + 2][lr] = a.z; As[lk + 3][lr] = a.w;
        Bs[lk + 0][lr] = b.x; Bs[lk + 1][lr] = b.y;
        Bs[lk + 2][lr] = b.z; Bs[lk + 3][lr] = b.w;
        __syncthreads();
        #pragma unroll
        for (int kk = 0; kk < 8; kk++) {
            float4 a0 = *(const float4*)&As[kk][ty * 4];
            float4 a1 = *(const float4*)&As[kk][64 + ty * 4];
            float4 b0 = *(const float4*)&Bs[kk][tx * 4];
            float4 b1 = *(const float4*)&Bs[kk][64 + tx * 4];
            float ar[8] = {a0.x, a0.y, a0.z, a0.w, a1.x, a1.y, a1.z, a1.w};
            float br[8] = {b0.x, b0.y, b0.z, b0.w, b1.x, b1.y, b1.z, b1.w};
            #pragma unroll
            for (int i = 0; i < 8; i++)
                #pragma unroll
                for (int j = 0; j < 8; j++) acc[i][j] += ar[i] * br[j];
        }
        __syncthreads();
        Ap += 8; Wp += 8;
    }

    #pragma unroll
    for (int i = 0; i < 8; i++) {
        int row = blockIdx.y * 128 + ((i < 4) ? (ty * 4 + i) : (64 + ty * 4 + (i - 4)));
        #pragma unroll
        for (int jg = 0; jg < 2; jg++) {
            int col = blockIdx.x * 128 + jg * 64 + tx * 4;
            float4 o;
            o.x = acc[i][jg * 4 + 0] + bias[col + 0];
            o.y = acc[i][jg * 4 + 1] + bias[col + 1];
            o.z = acc[i][jg * 4 + 2] + bias[col + 2];
            o.w = acc[i][jg * 4 + 3] + bias[col + 3];
            if (EPI == 1) {
                o.x = gelu_exact(o.x); o.y = gelu_exact(o.y);
                o.z = gelu_exact(o.z); o.w = gelu_exact(o.w);
            }
            if (EPI == 2) {
                float4 r4 = *(const float4*)(res + (size_t)row * N + col);
                o.x += r4.x; o.y += r4.y; o.z += r4.z; o.w += r4.w;
            }
            *(float4*)(C + (size_t)row * N + col) = o;
        }
    }
}

// ---------------- flash attention (fp32, causal, single head, D=256) ----------
// grid (64, 4): x = reversed query block (heavy first), y = batch. 256 threads.
__global__ void __launch_bounds__(256)
flash_kernel(const float* __restrict__ Q, const float* __restrict__ Kg,
             const float* __restrict__ Vg, float* __restrict__ O) {
    extern __shared__ float sm[];
    float* sQ = sm;                    // 64 x 256
    float* sK = sQ + 64 * 256;         // 64 x 257 (padded)
    float* sV = sK + 64 * KSTR;        // 64 x 256
    float* sP = sV + 64 * 256;         // 64 x 64

    int b = blockIdx.y;
    int qblk = 63 - blockIdx.x;        // heaviest query blocks first
    int tid = threadIdx.x;
    int tx = tid & 15, ty = tid >> 4;
    int r0 = ty * 4, c0 = tx * 4;

    size_t qbase = ((size_t)b * TT + (size_t)qblk * 64) * D;
    const float scale = 0.0625f;       // 1/sqrt(256)

    for (int i = tid; i < 64 * 64; i += 256) {
        float4 v = *(const float4*)(Q + qbase + (size_t)i * 4);
        v.x *= scale; v.y *= scale; v.z *= scale; v.w *= scale;
        *(float4*)(sQ + i * 4) = v;
    }

    float m[4], l[4];
    float4 acc[4][4];
    #pragma unroll
    for (int i = 0; i < 4; i++) {
        m[i] = -1e30f; l[i] = 0.f;
        #pragma unroll
        for (int j = 0; j < 4; j++) acc[i][j] = make_float4(0.f, 0.f, 0.f, 0.f);
    }

    for (int j = 0; j <= qblk; j++) {
        __syncthreads();   // protect sQ (first iter) and sK/sV from prior readers
        size_t kbase = ((size_t)b * TT + (size_t)j * 64) * D;
        for (int i = tid; i < 64 * 64; i += 256) {
            int s = i >> 6, dc = i & 63;
            float4 kv = *(const float4*)(Kg + kbase + (size_t)s * D + dc * 4);
            sK[s * KSTR + dc * 4 + 0] = kv.x;
            sK[s * KSTR + dc * 4 + 1] = kv.y;
            sK[s * KSTR + dc * 4 + 2] = kv.z;
            sK[s * KSTR + dc * 4 + 3] = kv.w;
            *(float4*)(sV + s * D + dc * 4) =
                *(const float4*)(Vg + kbase + (size_t)s * D + dc * 4);
        }
        __syncthreads();

        // S = Q K^T  (4x4 fragment per thread)
        float s4[4][4];
        #pragma unroll
        for (int i = 0; i < 4; i++)
            #pragma unroll
            for (int jj = 0; jj < 4; jj++) s4[i][jj] = 0.f;
        #pragma unroll 4
        for (int k = 0; k < D; k++) {
            float qv[4], kv[4];
            #pragma unroll
            for (int i = 0; i < 4; i++) {
                qv[i] = sQ[(r0 + i) * D + k];
                kv[i] = sK[(c0 + i) * KSTR + k];
            }
            #pragma unroll
            for (int i = 0; i < 4; i++)
                #pragma unroll
                for (int jj = 0; jj < 4; jj++) s4[i][jj] += qv[i] * kv[jj];
        }

        if (j == qblk) {  // only the diagonal block needs the causal mask
            #pragma unroll
            for (int i = 0; i < 4; i++)
                #pragma unroll
                for (int jj = 0; jj < 4; jj++)
                    if (c0 + jj > r0 + i) s4[i][jj] = -1e30f;
        }

        // online softmax per row (row group = 16 lanes within a half-warp)
        #pragma unroll
        for (int i = 0; i < 4; i++) {
            float mx = fmaxf(fmaxf(s4[i][0], s4[i][1]), fmaxf(s4[i][2], s4[i][3]));
            #pragma unroll
            for (int o = 8; o > 0; o >>= 1)
                mx = fmaxf(mx, __shfl_xor_sync(0xffffffffu, mx, o, 16));
            float nm = fmaxf(m[i], mx);
            float sc = __expf(m[i] - nm);
            float rs = 0.f;
            #pragma unroll
            for (int jj = 0; jj < 4; jj++) {
                float p = __expf(s4[i][jj] - nm);
                s4[i][jj] = p;
                rs += p;
            }
            #pragma unroll
            for (int o = 8; o > 0; o >>= 1)
                rs += __shfl_xor_sync(0xffffffffu, rs, o, 16);
            l[i] = l[i] * sc + rs;
            m[i] = nm;
            #pragma unroll
            for (int jj = 0; jj < 4; jj++) {
                acc[i][jj].x *= sc; acc[i][jj].y *= sc;
                acc[i][jj].z *= sc; acc[i][jj].w *= sc;
            }
            *(float4*)&sP[(r0 + i) * 64 + c0] =
                make_float4(s4[i][0], s4[i][1], s4[i][2], s4[i][3]);
        }
        __syncthreads();

        // O += P V   (thread owns rows r0..r0+3, cols {jj*64 + tx*4 .. +3})
        #pragma unroll 2
        for (int c = 0; c < 64; c++) {
            float pv[4];
            #pragma unroll
            for (int i = 0; i < 4; i++) pv[i] = sP[(r0 + i) * 64 + c];
            float4 vv[4];
            #pragma unroll
            for (int jj = 0; jj < 4; jj++)
                vv[jj] = *(const float4*)&sV[c * D + jj * 64 + tx * 4];
            #pragma unroll
            for (int i = 0; i < 4; i++)
                #pragma unroll
                for (int jj = 0; jj < 4; jj++) {
                    acc[i][jj].x += pv[i] * vv[jj].x;
                    acc[i][jj].y += pv[i] * vv[jj].y;
                    acc[i][jj].z += pv[i] * vv[jj].z;
                    acc[i][jj].w += pv[i] * vv[jj].w;
                }
        }
    }

    #pragma unroll
    for (int i = 0; i < 4; i++) {
        float inv = 1.0f / l[i];
        size_t orow = qbase + (size_t)(r0 + i) * D;
        #pragma unroll
        for (int jj = 0; jj < 4; jj++) {
            float4 o = acc[i][jj];
            o.x *= inv; o.y *= inv; o.z *= inv; o.w *= inv;
            *(float4*)(O + orow + jj * 64 + tx * 4) = o;
        }
    }
}

// ---------------- launch ----------------
extern "C" void kernel_launch(void* const* d_in, const int* in_sizes, int n_in,
                              void* d_out, int out_size) {
    const float* x   = (const float*)d_in[0];
    const float* anw = (const float*)d_in[1];
    const float* mnw = (const float*)d_in[2];
    const float* wq  = (const float*)d_in[3];
    const float* bq  = (const float*)d_in[4];
    const float* wk  = (const float*)d_in[5];
    const float* bk  = (const float*)d_in[6];
    const float* wv  = (const float*)d_in[7];
    const float* bv  = (const float*)d_in[8];
    const float* wo  = (const float*)d_in[9];
    const float* bo  = (const float*)d_in[10];
    const float* w1  = (const float*)d_in[11];
    const float* b1  = (const float*)d_in[12];
    const float* w2  = (const float*)d_in[13];
    const float* b2  = (const float*)d_in[14];
    float* out = (float*)d_out;

    float *xn, *q, *k, *v, *attn, *hn, *h;
    cudaGetSymbolAddress((void**)&xn,   g_xn);
    cudaGetSymbolAddress((void**)&q,    g_q);
    cudaGetSymbolAddress((void**)&k,    g_k);
    cudaGetSymbolAddress((void**)&v,    g_v);
    cudaGetSymbolAddress((void**)&attn, g_attn);
    cudaGetSymbolAddress((void**)&hn,   g_hn);
    cudaGetSymbolAddress((void**)&h,    g_h);

    const int SMEM_BYTES = (64 * 256 + 64 * KSTR + 64 * 256 + 64 * 64) * 4; // 213248
    cudaFuncSetAttribute(flash_kernel,
                         cudaFuncAttributeMaxDynamicSharedMemorySize, SMEM_BYTES);

    // 1) attn-norm
    rmsnorm_kernel<<<BT, 256>>>(x, anw, xn);
    // 2) q, k, v projections
    gemm_kernel<0><<<dim3(2, 128), 256>>>(xn, wq, bq, nullptr, q, BT, 256, 256);
    gemm_kernel<0><<<dim3(2, 128), 256>>>(xn, wk, bk, nullptr, k, BT, 256, 256);
    gemm_kernel<0><<<dim3(2, 128), 256>>>(xn, wv, bv, nullptr, v, BT, 256, 256);
    // 3) causal attention
    flash_kernel<<<dim3(64, NB), 256, SMEM_BYTES>>>(q, k, v, attn);
    // 4) output projection + residual  ->  out = x + attn @ wo^T + bo
    gemm_kernel<2><<<dim3(2, 128), 256>>>(attn, wo, bo, x, out, BT, 256, 256);
    // 5) mlp-norm
    rmsnorm_kernel<<<BT, 256>>>(out, mnw, hn);
    // 6) mlp up + gelu
    gemm_kernel<1><<<dim3(8, 128), 256>>>(hn, w1, b1, nullptr, h, BT, 1024, 256);
    // 7) mlp down + residual (in-place on out)
    gemm_kernel<2><<<dim3(2, 128), 256>>>(h, w2, b2, out, out, BT, 256, 1024);
}

// round 2
// speedup vs baseline: 2.6747x; 2.6747x over previous
#include <cuda_runtime.h>
#include <math.h>
#include <stdint.h>

#define D 256
#define TT 4096
#define NB 4
#define BT (NB*TT)      // 16384 rows

// -------- scratch (allocation-free: __device__ globals) --------
__device__ float g_xn[BT * D];
__device__ float g_q[BT * D];
__device__ float g_k[BT * D];
__device__ float g_v[BT * D];
__device__ float g_attn[BT * D];
__device__ float g_hn[BT * D];
__device__ float g_h[BT * 4 * D];
__device__ float g_wr[786432];   // tf32-rounded weights: wq,wk,wv,wo,w1,w2

// ---------------- helpers ----------------
__device__ __forceinline__ float tf32r(float x) {
    uint32_t u;
    asm("cvt.rna.tf32.f32 %0, %1;" : "=r"(u) : "f"(x));
    return __uint_as_float(u);
}

__device__ __forceinline__ void mma8(float* c, const float* a, const float* b) {
    asm volatile(
        "mma.sync.aligned.m16n8k8.row.col.f32.tf32.tf32.f32 "
        "{%0,%1,%2,%3}, {%4,%5,%6,%7}, {%8,%9}, {%0,%1,%2,%3};"
        : "+f"(c[0]), "+f"(c[1]), "+f"(c[2]), "+f"(c[3])
        : "r"(__float_as_uint(a[0])), "r"(__float_as_uint(a[1])),
          "r"(__float_as_uint(a[2])), "r"(__float_as_uint(a[3])),
          "r"(__float_as_uint(b[0])), "r"(__float_as_uint(b[1])));
}

__device__ __forceinline__ void cpa16(float* dst, const float* src) {
    uint32_t d = (uint32_t)__cvta_generic_to_shared(dst);
    asm volatile("cp.async.cg.shared.global [%0], [%1], 16;" :: "r"(d), "l"(src));
}

__device__ __forceinline__ float gelu_exact(float x) {
    return 0.5f * x * (1.0f + erff(x * 0.70710678118654752440f));
}

// ---------------- weight tf32 pre-round ----------------
__global__ void convert_w(const float* __restrict__ wq, const float* __restrict__ wk,
                          const float* __restrict__ wv, const float* __restrict__ wo,
                          const float* __restrict__ w1, const float* __restrict__ w2,
                          float* __restrict__ dst) {
    size_t i = ((size_t)blockIdx.x * 256 + threadIdx.x) * 4;   // 196608 float4s
    const float* src; size_t off = i;
    if      (i < 65536)  { src = wq; }
    else if (i < 131072) { src = wk; off = i - 65536; }
    else if (i < 196608) { src = wv; off = i - 131072; }
    else if (i < 262144) { src = wo; off = i - 196608; }
    else if (i < 524288) { src = w1; off = i - 262144; }
    else                 { src = w2; off = i - 524288; }
    float4 v = *(const float4*)(src + off);
    v.x = tf32r(v.x); v.y = tf32r(v.y); v.z = tf32r(v.z); v.w = tf32r(v.w);
    *(float4*)(dst + i) = v;
}

// ---------------- RMSNorm (output rounded to tf32) ----------------
__global__ void rmsnorm_kernel(const float* __restrict__ x,
                               const float* __restrict__ w,
                               float* __restrict__ out) {
    int row = blockIdx.x;
    int t = threadIdx.x;
    float v = x[(size_t)row * D + t];
    float ss = v * v;
    #pragma unroll
    for (int o = 16; o > 0; o >>= 1) ss += __shfl_xor_sync(0xffffffffu, ss, o);
    __shared__ float ws[8];
    if ((t & 31) == 0) ws[t >> 5] = ss;
    __syncthreads();
    float tot = 0.f;
    #pragma unroll
    for (int i = 0; i < 8; i++) tot += ws[i];
    float r = rsqrtf(tot * (1.0f / D) + 1e-6f);
    out[(size_t)row * D + t] = tf32r(v * r * w[t]);
}

// ---------------- tensor-core GEMM: C[M,N] = A[M,K] @ W[N,K]^T + bias ----
// EPI: 0 = bias (round tf32), 1 = bias+GELU (round tf32), 2 = bias+residual (fp32)
// block 128x128, 8 warps (2x4), warp tile 64x32, k-chunk 32, cp.async double buffer
template <int EPI>
__global__ void __launch_bounds__(256)
gemm_tc(const float* __restrict__ A, const float* __restrict__ W,
        const float* __restrict__ bias, const float* __restrict__ res,
        float* __restrict__ C, int M, int N, int K) {
    extern __shared__ float sm[];       // 2 buffers x (A 128x36 + B 128x36)
    const int tid = threadIdx.x;
    const int lane = tid & 31, wid = tid >> 5;
    const int wm = wid >> 2, wn = wid & 3;
    const int bm = blockIdx.y * 128, bn = blockIdx.x * 128;
    const int fr = tid >> 3, fc = (tid & 7) * 4;     // fill: row, col

    float acc[4][4][4];
    #pragma unroll
    for (int mf = 0; mf < 4; mf++)
        #pragma unroll
        for (int nf = 0; nf < 4; nf++)
            #pragma unroll
            for (int q = 0; q < 4; q++) acc[mf][nf][q] = 0.f;

    // initial fill (buf 0, kt 0)
    {
        float* sA = sm; float* sB = sm + 128 * 36;
        const float* Ap = A + (size_t)(bm + fr) * K + fc;
        const float* Wp = W + (size_t)(bn + fr) * K + fc;
        #pragma unroll
        for (int i = 0; i < 4; i++) {
            cpa16(&sA[(fr + i * 32) * 36 + fc], Ap + (size_t)i * 32 * K);
            cpa16(&sB[(fr + i * 32) * 36 + fc], Wp + (size_t)i * 32 * K);
        }
        asm volatile("cp.async.commit_group;");
    }

    int buf = 0;
    for (int kt = 0; kt < K; kt += 32) {
        if (kt + 32 < K) {
            float* sA = sm + (buf ^ 1) * 9216; float* sB = sA + 128 * 36;
            const float* Ap = A + (size_t)(bm + fr) * K + kt + 32 + fc;
            const float* Wp = W + (size_t)(bn + fr) * K + kt + 32 + fc;
            #pragma unroll
            for (int i = 0; i < 4; i++) {
                cpa16(&sA[(fr + i * 32) * 36 + fc], Ap + (size_t)i * 32 * K);
                cpa16(&sB[(fr + i * 32) * 36 + fc], Wp + (size_t)i * 32 * K);
            }
            asm volatile("cp.async.commit_group;");
            asm volatile("cp.async.wait_group 1;");
        } else {
            asm volatile("cp.async.wait_group 0;");
        }
        __syncthreads();

        const float* sA = sm + buf * 9216;
        const float* sB = sA + 128 * 36;
        #pragma unroll
        for (int ks = 0; ks < 4; ks++) {
            const int k0 = ks * 8;
            float a[4][4], b[4][2];
            #pragma unroll
            for (int mf = 0; mf < 4; mf++) {
                int row = wm * 64 + mf * 16 + (lane >> 2);
                a[mf][0] = sA[row * 36 + k0 + (lane & 3)];
                a[mf][1] = sA[(row + 8) * 36 + k0 + (lane & 3)];
                a[mf][2] = sA[row * 36 + k0 + 4 + (lane & 3)];
                a[mf][3] = sA[(row + 8) * 36 + k0 + 4 + (lane & 3)];
            }
            #pragma unroll
            for (int nf = 0; nf < 4; nf++) {
                int col = wn * 32 + nf * 8 + (lane >> 2);
                b[nf][0] = sB[col * 36 + k0 + (lane & 3)];
                b[nf][1] = sB[col * 36 + k0 + 4 + (lane & 3)];
            }
            #pragma unroll
            for (int mf = 0; mf < 4; mf++)
                #pragma unroll
                for (int nf = 0; nf < 4; nf++)
                    mma8(acc[mf][nf], a[mf], b[nf]);
        }
        __syncthreads();
        buf ^= 1;
    }

    // epilogue
    #pragma unroll
    for (int mf = 0; mf < 4; mf++) {
        #pragma unroll
        for (int nf = 0; nf < 4; nf++) {
            int row0 = bm + wm * 64 + mf * 16 + (lane >> 2);
            int col = bn + wn * 32 + nf * 8 + 2 * (lane & 3);
            float2 bv = *(const float2*)&bias[col];
            #pragma unroll
            for (int h = 0; h < 2; h++) {
                int row = row0 + h * 8;
                float2 o;
                o.x = acc[mf][nf][h * 2 + 0] + bv.x;
                o.y = acc[mf][nf][h * 2 + 1] + bv.y;
                if (EPI == 1) { o.x = gelu_exact(o.x); o.y = gelu_exact(o.y); }
                if (EPI == 2) {
                    float2 r2 = *(const float2*)(res + (size_t)row * N + col);
                    o.x += r2.x; o.y += r2.y;
                } else {
                    o.x = tf32r(o.x); o.y = tf32r(o.y);
                }
                *(float2*)(C + (size_t)row * N + col) = o;
            }
        }
    }
}

// ---------------- flash attention, tf32 tensor cores ----------------
// BM=BN=64, D=256. 8 warps: S phase 4(m)x2(n); PV phase computes O^T = V^T P^T
// with warp grid 4(d)x2(q). grid (64, NB), heavy query blocks first.
__global__ void __launch_bounds__(256)
flash_tc(const float* __restrict__ Q, const float* __restrict__ Kg,
         const float* __restrict__ Vg, float* __restrict__ O) {
    extern __shared__ float sm[];
    float* sQ = sm;                    // 64 x 264 (also reused as O staging)
    float* sK = sQ + 64 * 264;
    float* sV = sK + 64 * 264;
    float* sP = sV + 64 * 264;         // 64 x 68
    __shared__ float sM[64], sL[64], sSc[64], sRmax[128], sRsum[128];

    const int tid = threadIdx.x, lane = tid & 31, wid = tid >> 5;
    const int wm = wid >> 1, wn = wid & 1;
    const int b = blockIdx.y;
    const int qblk = 63 - blockIdx.x;
    const size_t qbase = ((size_t)b * TT + (size_t)qblk * 64) * D;

    // fill Q (prescaled by 1/16 — exact power of 2, stays tf32)
    #pragma unroll
    for (int p = 0; p < 16; p++) {
        int i = tid + p * 256;
        int s = i >> 6, dq = i & 63;
        float4 v = *(const float4*)(Q + qbase + (size_t)s * D + dq * 4);
        v.x *= 0.0625f; v.y *= 0.0625f; v.z *= 0.0625f; v.w *= 0.0625f;
        *(float4*)&sQ[s * 264 + dq * 4] = v;
    }
    if (tid < 64) { sM[tid] = -1e30f; sL[tid] = 0.f; }

    float oacc[4][4][4];
    #pragma unroll
    for (int mf = 0; mf < 4; mf++)
        #pragma unroll
        for (int nf = 0; nf < 4; nf++)
            #pragma unroll
            for (int q = 0; q < 4; q++) oacc[mf][nf][q] = 0.f;

    const int rA = wm * 16 + (lane >> 2), rB = rA + 8;

    for (int j = 0; j <= qblk; j++) {
        __syncthreads();                             // A: sK/sV/sP free, sQ ready
        size_t kbase = ((size_t)b * TT + (size_t)j * 64) * D;
        #pragma unroll
        for (int p = 0; p < 16; p++) {
            int i = tid + p * 256;
            int s = i >> 6, dq = i & 63;
            *(float4*)&sK[s * 264 + dq * 4] =
                *(const float4*)(Kg + kbase + (size_t)s * D + dq * 4);
            *(float4*)&sV[s * 264 + dq * 4] =
                *(const float4*)(Vg + kbase + (size_t)s * D + dq * 4);
        }
        __syncthreads();                             // B: tiles ready

        // ---- S = Q K^T (warp: 16 q-rows x 32 s-cols) ----
        float s4[4][4];
        #pragma unroll
        for (int nf = 0; nf < 4; nf++)
            #pragma unroll
            for (int q = 0; q < 4; q++) s4[nf][q] = 0.f;

        #pragma unroll 8
        for (int ks = 0; ks < 32; ks++) {
            const int k0 = ks * 8;
            float a[4], bfr[4][2];
            a[0] = sQ[rA * 264 + k0 + (lane & 3)];
            a[1] = sQ[rB * 264 + k0 + (lane & 3)];
            a[2] = sQ[rA * 264 + k0 + 4 + (lane & 3)];
            a[3] = sQ[rB * 264 + k0 + 4 + (lane & 3)];
            #pragma unroll
            for (int nf = 0; nf < 4; nf++) {
                int sc = wn * 32 + nf * 8 + (lane >> 2);
                bfr[nf][0] = sK[sc * 264 + k0 + (lane & 3)];
                bfr[nf][1] = sK[sc * 264 + k0 + 4 + (lane & 3)];
            }
            #pragma unroll
            for (int nf = 0; nf < 4; nf++) mma8(s4[nf], a, bfr[nf]);
        }

        if (j == qblk) {                              // causal mask (diag block)
            #pragma unroll
            for (int nf = 0; nf < 4; nf++) {
                int c0 = wn * 32 + nf * 8 + 2 * (lane & 3);
                if (c0 > rA)     s4[nf][0] = -1e30f;
                if (c0 + 1 > rA) s4[nf][1] = -1e30f;
                if (c0 > rB)     s4[nf][2] = -1e30f;
                if (c0 + 1 > rB) s4[nf][3] = -1e30f;
            }
        }

        // ---- row max (quad + cross-warp via smem) ----
        float mA = -1e30f, mB = -1e30f;
        #pragma unroll
        for (int nf = 0; nf < 4; nf++) {
            mA = fmaxf(mA, fmaxf(s4[nf][0], s4[nf][1]));
            mB = fmaxf(mB, fmaxf(s4[nf][2], s4[nf][3]));
        }
        mA = fmaxf(mA, __shfl_xor_sync(0xffffffffu, mA, 1));
        mA = fmaxf(mA, __shfl_xor_sync(0xffffffffu, mA, 2));
        mB = fmaxf(mB, __shfl_xor_sync(0xffffffffu, mB, 1));
        mB = fmaxf(mB, __shfl_xor_sync(0xffffffffu, mB, 2));
        if ((lane & 3) == 0) { sRmax[wn * 64 + rA] = mA; sRmax[wn * 64 + rB] = mB; }
        __syncthreads();                             // C
        if (tid < 64) {
            float bmx = fmaxf(sRmax[tid], sRmax[64 + tid]);
            float nm = fmaxf(sM[tid], bmx);
            sSc[tid] = __expf(sM[tid] - nm);
            sM[tid] = nm;
        }
        __syncthreads();                             // D
        const float nmA = sM[rA], nmB = sM[rB];
        float sumA = 0.f, sumB = 0.f;
        #pragma unroll
        for (int nf = 0; nf < 4; nf++) {
            int c0 = wn * 32 + nf * 8 + 2 * (lane & 3);
            float p0 = __expf(s4[nf][0] - nmA);
            float p1 = __expf(s4[nf][1] - nmA);
            float p2 = __expf(s4[nf][2] - nmB);
            float p3 = __expf(s4[nf][3] - nmB);
            sumA += p0 + p1; sumB += p2 + p3;
            sP[rA * 68 + c0] = tf32r(p0); sP[rA * 68 + c0 + 1] = tf32r(p1);
            sP[rB * 68 + c0] = tf32r(p2); sP[rB * 68 + c0 + 1] = tf32r(p3);
        }
        sumA += __shfl_xor_sync(0xffffffffu, sumA, 1);
        sumA += __shfl_xor_sync(0xffffffffu, sumA, 2);
        sumB += __shfl_xor_sync(0xffffffffu, sumB, 1);
        sumB += __shfl_xor_sync(0xffffffffu, sumB, 2);
        if ((lane & 3) == 0) { sRsum[wn * 64 + rA] = sumA; sRsum[wn * 64 + rB] = sumB; }
        __syncthreads();                             // E: sP ready, sums ready
        if (tid < 64) sL[tid] = sL[tid] * sSc[tid] + sRsum[tid] + sRsum[64 + tid];

        // ---- rescale O accumulators ----
        #pragma unroll
        for (int nf = 0; nf < 4; nf++) {
            int qc = wn * 32 + nf * 8 + 2 * (lane & 3);
            float sc0 = sSc[qc], sc1 = sSc[qc + 1];
            #pragma unroll
            for (int mf = 0; mf < 4; mf++) {
                oacc[mf][nf][0] *= sc0; oacc[mf][nf][1] *= sc1;
                oacc[mf][nf][2] *= sc0; oacc[mf][nf][3] *= sc1;
            }
        }

        // ---- O^T += V^T P^T (warp: 64 d-rows x 32 q-cols) ----
        #pragma unroll
        for (int ks = 0; ks < 8; ks++) {
            const int s0 = ks * 8;
            float a[4][4], bb[4][2];
            #pragma unroll
            for (int mf = 0; mf < 4; mf++) {
                int d0 = wm * 64 + mf * 16 + (lane >> 2);
                a[mf][0] = sV[(s0 + (lane & 3)) * 264 + d0];
                a[mf][1] = sV[(s0 + (lane & 3)) * 264 + d0 + 8];
                a[mf][2] = sV[(s0 + 4 + (lane & 3)) * 264 + d0];
                a[mf][3] = sV[(s0 + 4 + (lane & 3)) * 264 + d0 + 8];
            }
            #pragma unroll
            for (int nf = 0; nf < 4; nf++) {
                int q0 = wn * 32 + nf * 8 + (lane >> 2);
                bb[nf][0] = sP[q0 * 68 + s0 + (lane & 3)];
                bb[nf][1] = sP[q0 * 68 + s0 + 4 + (lane & 3)];
            }
            #pragma unroll
            for (int mf = 0; mf < 4; mf++)
                #pragma unroll
                for (int nf = 0; nf < 4; nf++)
                    mma8(oacc[mf][nf], a[mf], bb[nf]);
        }
    }

    __syncthreads();   // sL final, sQ free for staging
    #pragma unroll
    for (int nf = 0; nf < 4; nf++) {
        int qc = wn * 32 + nf * 8 + 2 * (lane & 3);
        float inv0 = 1.0f / sL[qc], inv1 = 1.0f / sL[qc + 1];
        #pragma unroll
        for (int mf = 0; mf < 4; mf++) {
            int d0 = wm * 64 + mf * 16 + (lane >> 2);
            sQ[qc * 264 + d0]           = tf32r(oacc[mf][nf][0] * inv0);
            sQ[(qc + 1) * 264 + d0]     = tf32r(oacc[mf][nf][1] * inv1);
            sQ[qc * 264 + d0 + 8]       = tf32r(oacc[mf][nf][2] * inv0);
            sQ[(qc + 1) * 264 + d0 + 8] = tf32r(oacc[mf][nf][3] * inv1);
        }
    }
    __syncthreads();
    #pragma unroll
    for (int p = 0; p < 16; p++) {
        int i = tid + p * 256;
        int s = i >> 6, dq = i & 63;
        *(float4*)(O + qbase + (size_t)s * D + dq * 4) =
            *(const float4*)&sQ[s * 264 + dq * 4];
    }
}

// ---------------- launch ----------------
extern "C" void kernel_launch(void* const* d_in, const int* in_sizes, int n_in,
                              void* d_out, int out_size) {
    const float* x   = (const float*)d_in[0];
    const float* anw = (const float*)d_in[1];
    const float* mnw = (const float*)d_in[2];
    const float* wq  = (const float*)d_in[3];
    const float* bq  = (const float*)d_in[4];
    const float* wk  = (const float*)d_in[5];
    const float* bk  = (const float*)d_in[6];
    const float* wv  = (const float*)d_in[7];
    const float* bv  = (const float*)d_in[8];
    const float* wo  = (const float*)d_in[9];
    const float* bo  = (const float*)d_in[10];
    const float* w1  = (const float*)d_in[11];
    const float* b1  = (const float*)d_in[12];
    const float* w2  = (const float*)d_in[13];
    const float* b2  = (const float*)d_in[14];
    float* out = (float*)d_out;

    float *xn, *q, *k, *v, *attn, *hn, *h, *wr;
    cudaGetSymbolAddress((void**)&xn,   g_xn);
    cudaGetSymbolAddress((void**)&q,    g_q);
    cudaGetSymbolAddress((void**)&k,    g_k);
    cudaGetSymbolAddress((void**)&v,    g_v);
    cudaGetSymbolAddress((void**)&attn, g_attn);
    cudaGetSymbolAddress((void**)&hn,   g_hn);
    cudaGetSymbolAddress((void**)&h,    g_h);
    cudaGetSymbolAddress((void**)&wr,   g_wr);

    const int GEMM_SMEM = 2 * 2 * 128 * 36 * 4;                     // 73728
    const int FLASH_SMEM = (3 * 64 * 264 + 64 * 68) * 4;            // 220160
    cudaFuncSetAttribute(gemm_tc<0>, cudaFuncAttributeMaxDynamicSharedMemorySize, GEMM_SMEM);
    cudaFuncSetAttribute(gemm_tc<1>, cudaFuncAttributeMaxDynamicSharedMemorySize, GEMM_SMEM);
    cudaFuncSetAttribute(gemm_tc<2>, cudaFuncAttributeMaxDynamicSharedMemorySize, GEMM_SMEM);
    cudaFuncSetAttribute(flash_tc,   cudaFuncAttributeMaxDynamicSharedMemorySize, FLASH_SMEM);

    // 0) round weights to tf32 once per replay
    convert_w<<<768, 256>>>(wq, wk, wv, wo, w1, w2, wr);
    // 1) attn-norm (tf32-rounded output)
    rmsnorm_kernel<<<BT, 256>>>(x, anw, xn);
    // 2) q, k, v projections
    gemm_tc<0><<<dim3(2, 128), 256, GEMM_SMEM>>>(xn, wr,          bq, nullptr, q, BT, 256, 256);
    gemm_tc<0><<<dim3(2, 128), 256, GEMM_SMEM>>>(xn, wr + 65536,  bk, nullptr, k, BT, 256, 256);
    gemm_tc<0><<<dim3(2, 128), 256, GEMM_SMEM>>>(xn, wr + 131072, bv, nullptr, v, BT, 256, 256);
    // 3) causal attention
    flash_tc<<<dim3(64, NB), 256, FLASH_SMEM>>>(q, k, v, attn);
    // 4) output projection + residual (fp32 out)
    gemm_tc<2><<<dim3(2, 128), 256, GEMM_SMEM>>>(attn, wr + 196608, bo, x, out, BT, 256, 256);
    // 5) mlp-norm
    rmsnorm_kernel<<<BT, 256>>>(out, mnw, hn);
    // 6) mlp up + gelu
    gemm_tc<1><<<dim3(8, 128), 256, GEMM_SMEM>>>(hn, wr + 262144, b1, nullptr, h, BT, 1024, 256);
    // 7) mlp down + residual (in-place on out)
    gemm_tc<2><<<dim3(2, 128), 256, GEMM_SMEM>>>(h, wr + 524288, b2, out, out, BT, 256, 1024);
}

// round 3
// speedup vs baseline: 3.2709x; 1.2229x over previous
#include <cuda_runtime.h>
#include <math.h>
#include <stdint.h>

#define D 256
#define TT 4096
#define NB 4
#define BT (NB*TT)      // 16384 rows

// -------- scratch (allocation-free: __device__ globals) --------
__device__ float g_xn[BT * D];
__device__ float g_q[BT * D];
__device__ float g_k[BT * D];
__device__ float g_v[BT * D];
__device__ float g_attn[BT * D];
__device__ float g_hn[BT * D];
__device__ float g_h[BT * 4 * D];
__device__ float g_wr[786432];   // tf32-rounded weights: wq,wk,wv,wo,w1,w2

// ---------------- helpers ----------------
__device__ __forceinline__ float tf32r(float x) {
    uint32_t u;
    asm("cvt.rna.tf32.f32 %0, %1;" : "=r"(u) : "f"(x));
    return __uint_as_float(u);
}

__device__ __forceinline__ void mma8(float* c, const float* a, const float* b) {
    asm volatile(
        "mma.sync.aligned.m16n8k8.row.col.f32.tf32.tf32.f32 "
        "{%0,%1,%2,%3}, {%4,%5,%6,%7}, {%8,%9}, {%0,%1,%2,%3};"
        : "+f"(c[0]), "+f"(c[1]), "+f"(c[2]), "+f"(c[3])
        : "r"(__float_as_uint(a[0])), "r"(__float_as_uint(a[1])),
          "r"(__float_as_uint(a[2])), "r"(__float_as_uint(a[3])),
          "r"(__float_as_uint(b[0])), "r"(__float_as_uint(b[1])));
}

__device__ __forceinline__ void cpa16(float* dst, const float* src) {
    uint32_t d = (uint32_t)__cvta_generic_to_shared(dst);
    asm volatile("cp.async.cg.shared.global [%0], [%1], 16;" :: "r"(d), "l"(src));
}
#define CP_COMMIT()  asm volatile("cp.async.commit_group;")
#define CP_WAIT(n)   asm volatile("cp.async.wait_group %0;" :: "n"(n) : "memory")

__device__ __forceinline__ float gelu_exact(float x) {
    return 0.5f * x * (1.0f + erff(x * 0.70710678118654752440f));
}

// ---------------- weight tf32 pre-round ----------------
__global__ void convert_w(const float* __restrict__ wq, const float* __restrict__ wk,
                          const float* __restrict__ wv, const float* __restrict__ wo,
                          const float* __restrict__ w1, const float* __restrict__ w2,
                          float* __restrict__ dst) {
    size_t i = ((size_t)blockIdx.x * 256 + threadIdx.x) * 4;
    const float* src; size_t off = i;
    if      (i < 65536)  { src = wq; }
    else if (i < 131072) { src = wk; off = i - 65536; }
    else if (i < 196608) { src = wv; off = i - 131072; }
    else if (i < 262144) { src = wo; off = i - 196608; }
    else if (i < 524288) { src = w1; off = i - 262144; }
    else                 { src = w2; off = i - 524288; }
    float4 v = *(const float4*)(src + off);
    v.x = tf32r(v.x); v.y = tf32r(v.y); v.z = tf32r(v.z); v.w = tf32r(v.w);
    *(float4*)(dst + i) = v;
}

// ---------------- RMSNorm (output rounded to tf32) ----------------
__global__ void rmsnorm_kernel(const float* __restrict__ x,
                               const float* __restrict__ w,
                               float* __restrict__ out) {
    int row = blockIdx.x;
    int t = threadIdx.x;
    float v = x[(size_t)row * D + t];
    float ss = v * v;
    #pragma unroll
    for (int o = 16; o > 0; o >>= 1) ss += __shfl_xor_sync(0xffffffffu, ss, o);
    __shared__ float ws[8];
    if ((t & 31) == 0) ws[t >> 5] = ss;
    __syncthreads();
    float tot = 0.f;
    #pragma unroll
    for (int i = 0; i < 8; i++) tot += ws[i];
    float r = rsqrtf(tot * (1.0f / D) + 1e-6f);
    out[(size_t)row * D + t] = tf32r(v * r * w[t]);
}

// ---------------- tensor-core GEMM body: block 128x128, 4 warps, warp 64x64 --
// EPI: 0 = bias (round tf32), 1 = bias+GELU (round tf32), 2 = bias+residual (fp32)
template <int EPI>
__device__ __forceinline__ void
gemm_body(const float* __restrict__ A, const float* __restrict__ W,
          const float* __restrict__ bias, const float* __restrict__ res,
          float* __restrict__ C, int N, int K) {
    extern __shared__ float sm[];       // 2 buf x (A 128x36 + B 128x36)
    const int tid = threadIdx.x;
    const int lane = tid & 31, wid = tid >> 5;
    const int wm = wid >> 1, wn = wid & 1;
    const int g = lane >> 2, t = lane & 3;
    const int bm = blockIdx.y * 128, bn = blockIdx.x * 128;
    const int fr = tid >> 3, fc = (tid & 7) * 4;     // 16 fill rows, 8 col-groups

    float acc[4][8][4];
    #pragma unroll
    for (int mf = 0; mf < 4; mf++)
        #pragma unroll
        for (int nf = 0; nf < 8; nf++)
            #pragma unroll
            for (int q = 0; q < 4; q++) acc[mf][nf][q] = 0.f;

    {   // initial fill (buf 0)
        float* sA = sm; float* sB = sm + 128 * 36;
        const float* Ap = A + (size_t)(bm + fr) * K + fc;
        const float* Wp = W + (size_t)(bn + fr) * K + fc;
        #pragma unroll
        for (int i = 0; i < 8; i++) {
            cpa16(&sA[(fr + i * 16) * 36 + fc], Ap + (size_t)i * 16 * K);
            cpa16(&sB[(fr + i * 16) * 36 + fc], Wp + (size_t)i * 16 * K);
        }
        CP_COMMIT();
    }

    int buf = 0;
    for (int kt = 0; kt < K; kt += 32) {
        if (kt + 32 < K) {
            float* sA = sm + (buf ^ 1) * 9216; float* sB = sA + 128 * 36;
            const float* Ap = A + (size_t)(bm + fr) * K + kt + 32 + fc;
            const float* Wp = W + (size_t)(bn + fr) * K + kt + 32 + fc;
            #pragma unroll
            for (int i = 0; i < 8; i++) {
                cpa16(&sA[(fr + i * 16) * 36 + fc], Ap + (size_t)i * 16 * K);
                cpa16(&sB[(fr + i * 16) * 36 + fc], Wp + (size_t)i * 16 * K);
            }
            CP_COMMIT();
            CP_WAIT(1);
        } else {
            CP_WAIT(0);
        }
        __syncthreads();

        const float* sA = sm + buf * 9216;
        const float* sB = sA + 128 * 36;
        #pragma unroll
        for (int ks = 0; ks < 4; ks++) {
            const int k0 = ks * 8;
            float a[4][4], b[8][2];
            #pragma unroll
            for (int mf = 0; mf < 4; mf++) {
                int row = wm * 64 + mf * 16 + g;
                a[mf][0] = sA[row * 36 + k0 + t];
                a[mf][1] = sA[(row + 8) * 36 + k0 + t];
                a[mf][2] = sA[row * 36 + k0 + 4 + t];
                a[mf][3] = sA[(row + 8) * 36 + k0 + 4 + t];
            }
            #pragma unroll
            for (int nf = 0; nf < 8; nf++) {
                int col = wn * 64 + nf * 8 + g;
                b[nf][0] = sB[col * 36 + k0 + t];
                b[nf][1] = sB[col * 36 + k0 + 4 + t];
            }
            #pragma unroll
            for (int mf = 0; mf < 4; mf++)
                #pragma unroll
                for (int nf = 0; nf < 8; nf++)
                    mma8(acc[mf][nf], a[mf], b[nf]);
        }
        __syncthreads();
        buf ^= 1;
    }

    #pragma unroll
    for (int mf = 0; mf < 4; mf++) {
        #pragma unroll
        for (int nf = 0; nf < 8; nf++) {
            int row0 = bm + wm * 64 + mf * 16 + g;
            int col = bn + wn * 64 + nf * 8 + 2 * t;
            float2 bv = *(const float2*)&bias[col];
            #pragma unroll
            for (int h = 0; h < 2; h++) {
                int row = row0 + h * 8;
                float2 o;
                o.x = acc[mf][nf][h * 2 + 0] + bv.x;
                o.y = acc[mf][nf][h * 2 + 1] + bv.y;
                if (EPI == 1) { o.x = gelu_exact(o.x); o.y = gelu_exact(o.y); }
                if (EPI == 2) {
                    float2 r2 = *(const float2*)(res + (size_t)row * N + col);
                    o.x += r2.x; o.y += r2.y;
                } else {
                    o.x = tf32r(o.x); o.y = tf32r(o.y);
                }
                *(float2*)(C + (size_t)row * N + col) = o;
            }
        }
    }
}

template <int EPI>
__global__ void __launch_bounds__(128)
gemm_tc(const float* __restrict__ A, const float* __restrict__ W,
        const float* __restrict__ bias, const float* __restrict__ res,
        float* __restrict__ C, int N, int K) {
    gemm_body<EPI>(A, W, bias, res, C, N, K);
}

// fused QKV: blockIdx.z selects projection
__global__ void __launch_bounds__(128)
gemm_qkv(const float* __restrict__ A, const float* __restrict__ wr,
         const float* __restrict__ bq, const float* __restrict__ bk,
         const float* __restrict__ bv,
         float* __restrict__ q, float* __restrict__ k, float* __restrict__ v) {
    int z = blockIdx.z;
    const float* W = wr + (size_t)z * 65536;
    const float* bias = (z == 0) ? bq : ((z == 1) ? bk : bv);
    float* C = (z == 0) ? q : ((z == 1) ? k : v);
    gemm_body<0>(A, W, bias, nullptr, C, 256, 256);
}

// ---------------- flash attention, tf32 + cp.async chunk pipeline ----------
// BM=BN=64, D=256 split into two 128-chunks. 8 warps.
#define QS 132
#define VS 136
#define PS 68
#define QCH (64*QS)     // 8448 floats per chunk
#define VCH (64*VS)     // 8704

__global__ void __launch_bounds__(256)
flash_tc(const float* __restrict__ Q, const float* __restrict__ Kg,
         const float* __restrict__ Vg, float* __restrict__ O) {
    extern __shared__ float sm[];
    float* sQ = sm;                    // 2 chunks 64x132
    float* sK = sQ + 2 * QCH;          // 2 chunks 64x132
    float* sV = sK + 2 * QCH;          // 2 chunks 64x136
    float* sP = sV + 2 * VCH;          // 64x68
    __shared__ float sM[64], sL[64], sSc[64], sRmax[128], sRsum[128];

    const int tid = threadIdx.x, lane = tid & 31, wid = tid >> 5;
    const int wm = wid >> 1, wn = wid & 1;
    const int g = lane >> 2, t = lane & 3;
    const int b = blockIdx.y;
    const int qblk = 63 - blockIdx.x;
    const size_t qbase = ((size_t)b * TT + (size_t)qblk * 64) * D;
    const size_t bbase = (size_t)b * TT * D;

    // prologue: Q (both chunks) + K(0) chunks, one group
    #pragma unroll
    for (int c = 0; c < 2; c++)
        #pragma unroll
        for (int p = 0; p < 8; p++) {
            int i = tid + p * 256;           // 0..2047
            int row = i >> 5, cv = i & 31;
            cpa16(&sQ[c * QCH + row * QS + cv * 4],
                  Q + qbase + (size_t)row * D + c * 128 + cv * 4);
            cpa16(&sK[c * QCH + row * QS + cv * 4],
                  Kg + bbase + (size_t)row * D + c * 128 + cv * 4);
        }
    CP_COMMIT();

    if (tid < 64) { sM[tid] = -1e30f; sL[tid] = 0.f; }

    float oacc[4][4][4];
    #pragma unroll
    for (int mf = 0; mf < 4; mf++)
        #pragma unroll
        for (int nf = 0; nf < 4; nf++)
            #pragma unroll
            for (int q = 0; q < 4; q++) oacc[mf][nf][q] = 0.f;

    const int rA = wm * 16 + g, rB = rA + 8;

    for (int j = 0; j <= qblk; j++) {
        __syncthreads();                              // A: V bufs + P free
        size_t kbase = bbase + (size_t)j * 64 * D;
        // issue V(j)
        #pragma unroll
        for (int c = 0; c < 2; c++)
            #pragma unroll
            for (int p = 0; p < 8; p++) {
                int i = tid + p * 256;
                int row = i >> 5, cv = i & 31;
                cpa16(&sV[c * VCH + row * VS + cv * 4],
                      Vg + kbase + (size_t)row * D + c * 128 + cv * 4);
            }
        CP_COMMIT();
        CP_WAIT(1);                                   // K(j) (and Q) arrived
        __syncthreads();                              // B

        // ---- S = Q K^T ----
        float s4[4][4];
        #pragma unroll
        for (int nf = 0; nf < 4; nf++)
            #pragma unroll
            for (int q = 0; q < 4; q++) s4[nf][q] = 0.f;

        #pragma unroll
        for (int ch = 0; ch < 2; ch++) {
            const float* sQc = sQ + ch * QCH;
            const float* sKc = sK + ch * QCH;
            #pragma unroll 4
            for (int ks = 0; ks < 16; ks++) {
                const int k0 = ks * 8;
                float a[4], bfr[4][2];
                a[0] = sQc[rA * QS + k0 + t];
                a[1] = sQc[rB * QS + k0 + t];
                a[2] = sQc[rA * QS + k0 + 4 + t];
                a[3] = sQc[rB * QS + k0 + 4 + t];
                #pragma unroll
                for (int nf = 0; nf < 4; nf++) {
                    int sc = wn * 32 + nf * 8 + g;
                    bfr[nf][0] = sKc[sc * QS + k0 + t];
                    bfr[nf][1] = sKc[sc * QS + k0 + 4 + t];
                }
                #pragma unroll
                for (int nf = 0; nf < 4; nf++) mma8(s4[nf], a, bfr[nf]);
            }
        }
        #pragma unroll
        for (int nf = 0; nf < 4; nf++)
            #pragma unroll
            for (int q = 0; q < 4; q++) s4[nf][q] *= 0.0625f;

        if (j == qblk) {                              // causal mask
            #pragma unroll
            for (int nf = 0; nf < 4; nf++) {
                int c0 = wn * 32 + nf * 8 + 2 * t;
                if (c0 > rA)     s4[nf][0] = -1e30f;
                if (c0 + 1 > rA) s4[nf][1] = -1e30f;
                if (c0 > rB)     s4[nf][2] = -1e30f;
                if (c0 + 1 > rB) s4[nf][3] = -1e30f;
            }
        }

        // ---- row max ----
        float mA = -1e30f, mB = -1e30f;
        #pragma unroll
        for (int nf = 0; nf < 4; nf++) {
            mA = fmaxf(mA, fmaxf(s4[nf][0], s4[nf][1]));
            mB = fmaxf(mB, fmaxf(s4[nf][2], s4[nf][3]));
        }
        mA = fmaxf(mA, __shfl_xor_sync(0xffffffffu, mA, 1));
        mA = fmaxf(mA, __shfl_xor_sync(0xffffffffu, mA, 2));
        mB = fmaxf(mB, __shfl_xor_sync(0xffffffffu, mB, 1));
        mB = fmaxf(mB, __shfl_xor_sync(0xffffffffu, mB, 2));
        if (t == 0) { sRmax[wn * 64 + rA] = mA; sRmax[wn * 64 + rB] = mB; }
        __syncthreads();                              // C: K reads done
        if (tid < 64) {
            float bmx = fmaxf(sRmax[tid], sRmax[64 + tid]);
            float nm = fmaxf(sM[tid], bmx);
            sSc[tid] = __expf(sM[tid] - nm);
            sM[tid] = nm;
        }
        __syncthreads();                              // D

        // issue K(j+1) (or empty group)
        if (j < qblk) {
            size_t knext = bbase + (size_t)(j + 1) * 64 * D;
            #pragma unroll
            for (int c = 0; c < 2; c++)
                #pragma unroll
                for (int p = 0; p < 8; p++) {
                    int i = tid + p * 256;
                    int row = i >> 5, cv = i & 31;
                    cpa16(&sK[c * QCH + row * QS + cv * 4],
                          Kg + knext + (size_t)row * D + c * 128 + cv * 4);
                }
        }
        CP_COMMIT();

        const float nmA = sM[rA], nmB = sM[rB];
        float sumA = 0.f, sumB = 0.f;
        #pragma unroll
        for (int nf = 0; nf < 4; nf++) {
            int c0 = wn * 32 + nf * 8 + 2 * t;
            float p0 = __expf(s4[nf][0] - nmA);
            float p1 = __expf(s4[nf][1] - nmA);
            float p2 = __expf(s4[nf][2] - nmB);
            float p3 = __expf(s4[nf][3] - nmB);
            sumA += p0 + p1; sumB += p2 + p3;
            sP[rA * PS + c0] = tf32r(p0); sP[rA * PS + c0 + 1] = tf32r(p1);
            sP[rB * PS + c0] = tf32r(p2); sP[rB * PS + c0 + 1] = tf32r(p3);
        }
        sumA += __shfl_xor_sync(0xffffffffu, sumA, 1);
        sumA += __shfl_xor_sync(0xffffffffu, sumA, 2);
        sumB += __shfl_xor_sync(0xffffffffu, sumB, 1);
        sumB += __shfl_xor_sync(0xffffffffu, sumB, 2);
        if (t == 0) { sRsum[wn * 64 + rA] = sumA; sRsum[wn * 64 + rB] = sumB; }

        CP_WAIT(1);                                   // V(j) done (K(j+1) pending)
        __syncthreads();                              // E: sP, sums, V visible
        if (tid < 64) sL[tid] = sL[tid] * sSc[tid] + sRsum[tid] + sRsum[64 + tid];

        // rescale O accumulators
        #pragma unroll
        for (int nf = 0; nf < 4; nf++) {
            int qc = wn * 32 + nf * 8 + 2 * t;
            float sc0 = sSc[qc], sc1 = sSc[qc + 1];
            #pragma unroll
            for (int mf = 0; mf < 4; mf++) {
                oacc[mf][nf][0] *= sc0; oacc[mf][nf][1] *= sc1;
                oacc[mf][nf][2] *= sc0; oacc[mf][nf][3] *= sc1;
            }
        }

        // ---- O^T += V^T P^T ----
        const float* sVc = sV + (wm >> 1) * VCH;
        const int d0b = (wm & 1) * 64;
        #pragma unroll
        for (int ks = 0; ks < 8; ks++) {
            const int s0 = ks * 8;
            float a[4][4], bb[4][2];
            #pragma unroll
            for (int mf = 0; mf < 4; mf++) {
                int d0 = d0b + mf * 16 + g;
                a[mf][0] = sVc[(s0 + t) * VS + d0];
                a[mf][1] = sVc[(s0 + t) * VS + d0 + 8];
                a[mf][2] = sVc[(s0 + 4 + t) * VS + d0];
                a[mf][3] = sVc[(s0 + 4 + t) * VS + d0 + 8];
            }
            #pragma unroll
            for (int nf = 0; nf < 4; nf++) {
                int q0 = wn * 32 + nf * 8 + g;
                bb[nf][0] = sP[q0 * PS + s0 + t];
                bb[nf][1] = sP[q0 * PS + s0 + 4 + t];
            }
            #pragma unroll
            for (int mf = 0; mf < 4; mf++)
                #pragma unroll
                for (int nf = 0; nf < 4; nf++)
                    mma8(oacc[mf][nf], a[mf], bb[nf]);
        }
    }

    __syncthreads();   // sL final, sQ free for staging
    #pragma unroll
    for (int nf = 0; nf < 4; nf++) {
        int qc = wn * 32 + nf * 8 + 2 * t;
        float inv0 = 1.0f / sL[qc], inv1 = 1.0f / sL[qc + 1];
        float* sQc = sQ + (wm >> 1) * QCH;
        #pragma unroll
        for (int mf = 0; mf < 4; mf++) {
            int dl = (wm & 1) * 64 + mf * 16 + g;
            sQc[qc * QS + dl]           = tf32r(oacc[mf][nf][0] * inv0);
            sQc[(qc + 1) * QS + dl]     = tf32r(oacc[mf][nf][1] * inv1);
            sQc[qc * QS + dl + 8]       = tf32r(oacc[mf][nf][2] * inv0);
            sQc[(qc + 1) * QS + dl + 8] = tf32r(oacc[mf][nf][3] * inv1);
        }
    }
    __syncthreads();
    #pragma unroll
    for (int p = 0; p < 16; p++) {
        int i = tid + p * 256;
        int s = i >> 6, dq = i & 63;        // dq*4 = col
        int ch = dq >> 5, off = (dq & 31) * 4;
        *(float4*)(O + qbase + (size_t)s * D + dq * 4) =
            *(const float4*)&sQ[ch * QCH + s * QS + off];
    }
}

// ---------------- launch ----------------
extern "C" void kernel_launch(void* const* d_in, const int* in_sizes, int n_in,
                              void* d_out, int out_size) {
    const float* x   = (const float*)d_in[0];
    const float* anw = (const float*)d_in[1];
    const float* mnw = (const float*)d_in[2];
    const float* wq  = (const float*)d_in[3];
    const float* bq  = (const float*)d_in[4];
    const float* wk  = (const float*)d_in[5];
    const float* bk  = (const float*)d_in[6];
    const float* wv  = (const float*)d_in[7];
    const float* bv  = (const float*)d_in[8];
    const float* wo  = (const float*)d_in[9];
    const float* bo  = (const float*)d_in[10];
    const float* w1  = (const float*)d_in[11];
    const float* b1  = (const float*)d_in[12];
    const float* w2  = (const float*)d_in[13];
    const float* b2  = (const float*)d_in[14];
    float* out = (float*)d_out;

    float *xn, *q, *k, *v, *attn, *hn, *h, *wr;
    cudaGetSymbolAddress((void**)&xn,   g_xn);
    cudaGetSymbolAddress((void**)&q,    g_q);
    cudaGetSymbolAddress((void**)&k,    g_k);
    cudaGetSymbolAddress((void**)&v,    g_v);
    cudaGetSymbolAddress((void**)&attn, g_attn);
    cudaGetSymbolAddress((void**)&hn,   g_hn);
    cudaGetSymbolAddress((void**)&h,    g_h);
    cudaGetSymbolAddress((void**)&wr,   g_wr);

    const int GEMM_SMEM  = 2 * 2 * 128 * 36 * 4;                    // 73728
    const int FLASH_SMEM = (2 * QCH + 2 * QCH + 2 * VCH + 64 * PS) * 4; // 222208
    cudaFuncSetAttribute(gemm_tc<1>, cudaFuncAttributeMaxDynamicSharedMemorySize, GEMM_SMEM);
    cudaFuncSetAttribute(gemm_tc<2>, cudaFuncAttributeMaxDynamicSharedMemorySize, GEMM_SMEM);
    cudaFuncSetAttribute(gemm_qkv,   cudaFuncAttributeMaxDynamicSharedMemorySize, GEMM_SMEM);
    cudaFuncSetAttribute(flash_tc,   cudaFuncAttributeMaxDynamicSharedMemorySize, FLASH_SMEM);

    // 0) round weights to tf32
    convert_w<<<768, 256>>>(wq, wk, wv, wo, w1, w2, wr);
    // 1) attn-norm
    rmsnorm_kernel<<<BT, 256>>>(x, anw, xn);
    // 2) fused q,k,v projections
    gemm_qkv<<<dim3(2, 128, 3), 128, GEMM_SMEM>>>(xn, wr, bq, bk, bv, q, k, v);
    // 3) causal attention
    flash_tc<<<dim3(64, NB), 256, FLASH_SMEM>>>(q, k, v, attn);
    // 4) output projection + residual
    gemm_tc<2><<<dim3(2, 128), 128, GEMM_SMEM>>>(attn, wr + 196608, bo, x, out, 256, 256);
    // 5) mlp-norm
    rmsnorm_kernel<<<BT, 256>>>(out, mnw, hn);
    // 6) mlp up + gelu
    gemm_tc<1><<<dim3(8, 128), 128, GEMM_SMEM>>>(hn, wr + 262144, b1, nullptr, h, 1024, 256);
    // 7) mlp down + residual
    gemm_tc<2><<<dim3(2, 128), 128, GEMM_SMEM>>>(h, wr + 524288, b2, out, out, 256, 1024);
}

// round 6
// speedup vs baseline: 6.2483x; 1.9102x over previous
#include <cuda_runtime.h>
#include <cuda_bf16.h>
#include <math.h>
#include <stdint.h>

#define D 256
#define TT 4096
#define NB 4
#define BT (NB*TT)      // 16384 rows

// -------- scratch (allocation-free: __device__ globals) --------
__device__ __nv_bfloat16 g_xnb[BT * D];
__device__ __nv_bfloat16 g_qb[BT * D];
__device__ __nv_bfloat16 g_kb[BT * D];
__device__ __nv_bfloat16 g_vb[BT * D];
__device__ __nv_bfloat16 g_attnb[BT * D];
__device__ __nv_bfloat16 g_hnb[BT * D];
__device__ __nv_bfloat16 g_hb[BT * 4 * D];
__device__ __nv_bfloat16 g_wb[786432];   // bf16 weights: wq,wk,wv,wo,w1,w2

// ---------------- helpers ----------------
__device__ __forceinline__ void mma16(float* c, uint32_t a0, uint32_t a1,
                                      uint32_t a2, uint32_t a3,
                                      uint32_t b0, uint32_t b1) {
    asm volatile(
        "mma.sync.aligned.m16n8k16.row.col.f32.bf16.bf16.f32 "
        "{%0,%1,%2,%3}, {%4,%5,%6,%7}, {%8,%9}, {%0,%1,%2,%3};"
        : "+f"(c[0]), "+f"(c[1]), "+f"(c[2]), "+f"(c[3])
        : "r"(a0), "r"(a1), "r"(a2), "r"(a3), "r"(b0), "r"(b1));
}

__device__ __forceinline__ void cpa16(void* dst, const void* src) {
    uint32_t d = (uint32_t)__cvta_generic_to_shared(dst);
    asm volatile("cp.async.cg.shared.global [%0], [%1], 16;" :: "r"(d), "l"(src));
}
#define CP_COMMIT()  asm volatile("cp.async.commit_group;")
#define CP_WAIT(n)   asm volatile("cp.async.wait_group %0;" :: "n"(n) : "memory")

__device__ __forceinline__ uint32_t bf2u(__nv_bfloat162 h) {
    uint32_t u; *(__nv_bfloat162*)&u = h; return u;
}

__device__ __forceinline__ float gelu_exact(float x) {
    return 0.5f * x * (1.0f + erff(x * 0.70710678118654752440f));
}

// ---------------- weight bf16 pre-round ----------------
__global__ void convert_w(const float* __restrict__ wq, const float* __restrict__ wk,
                          const float* __restrict__ wv, const float* __restrict__ wo,
                          const float* __restrict__ w1, const float* __restrict__ w2,
                          __nv_bfloat16* __restrict__ dst) {
    size_t i = ((size_t)blockIdx.x * 256 + threadIdx.x) * 4;
    const float* src; size_t off = i;
    if      (i < 65536)  { src = wq; }
    else if (i < 131072) { src = wk; off = i - 65536; }
    else if (i < 196608) { src = wv; off = i - 131072; }
    else if (i < 262144) { src = wo; off = i - 196608; }
    else if (i < 524288) { src = w1; off = i - 262144; }
    else                 { src = w2; off = i - 524288; }
    float4 v = *(const float4*)(src + off);
    uint2 pk;
    pk.x = bf2u(__floats2bfloat162_rn(v.x, v.y));
    pk.y = bf2u(__floats2bfloat162_rn(v.z, v.w));
    *(uint2*)(dst + i) = pk;
}

// ---------------- RMSNorm (fp32 in, bf16 out), one warp per row ------------
__global__ void rmsnorm_kernel(const float* __restrict__ x,
                               const float* __restrict__ w,
                               __nv_bfloat16* __restrict__ out) {
    int row = blockIdx.x * 8 + (threadIdx.x >> 5);
    int lane = threadIdx.x & 31;
    const float* xr = x + (size_t)row * D + lane * 8;
    float4 a = *(const float4*)xr;
    float4 b = *(const float4*)(xr + 4);
    float ss = a.x*a.x + a.y*a.y + a.z*a.z + a.w*a.w
             + b.x*b.x + b.y*b.y + b.z*b.z + b.w*b.w;
    #pragma unroll
    for (int o = 16; o > 0; o >>= 1) ss += __shfl_xor_sync(0xffffffffu, ss, o);
    float r = rsqrtf(ss * (1.0f / D) + 1e-6f);
    float4 wa = *(const float4*)(w + lane * 8);
    float4 wb = *(const float4*)(w + lane * 8 + 4);
    uint4 pk;
    pk.x = bf2u(__floats2bfloat162_rn(a.x * r * wa.x, a.y * r * wa.y));
    pk.y = bf2u(__floats2bfloat162_rn(a.z * r * wa.z, a.w * r * wa.w));
    pk.z = bf2u(__floats2bfloat162_rn(b.x * r * wb.x, b.y * r * wb.y));
    pk.w = bf2u(__floats2bfloat162_rn(b.z * r * wb.z, b.w * r * wb.w));
    *(uint4*)(out + (size_t)row * D + lane * 8) = pk;
}

// ---------------- bf16 tensor-core GEMM: C = A[M,K] @ W[N,K]^T + bias ------
// block 128x128, 256 threads (8 warps 2x4), warp 64x32, k-chunk 32, double buf
// EPI: 0 = bias -> bf16, 1 = bias+GELU -> bf16, 2 = bias+residual -> fp32
template <int EPI>
__device__ __forceinline__ void
gemm_body(const __nv_bfloat16* __restrict__ A, const __nv_bfloat16* __restrict__ W,
          const float* __restrict__ bias, const float* __restrict__ res,
          void* __restrict__ Cv, int N, int K) {
    extern __shared__ __align__(16) __nv_bfloat16 smh[];   // 2 x (A 128x40 + B 128x40)
    const int tid = threadIdx.x, lane = tid & 31, wid = tid >> 5;
    const int wm = wid >> 2, wn = wid & 3;
    const int g = lane >> 2, t = lane & 3;
    const int bm = blockIdx.y * 128, bn = blockIdx.x * 128;

    float acc[4][4][4];
    #pragma unroll
    for (int mf = 0; mf < 4; mf++)
        #pragma unroll
        for (int nf = 0; nf < 4; nf++)
            #pragma unroll
            for (int q = 0; q < 4; q++) acc[mf][nf][q] = 0.f;

    #define GFILL(bufp, kt) do {                                              \
        __nv_bfloat16* sA_ = smh + (bufp) * 10240;                            \
        __nv_bfloat16* sB_ = sA_ + 5120;                                      \
        _Pragma("unroll")                                                     \
        for (int p = 0; p < 2; p++) {                                         \
            int i = tid + p * 256; int r = i >> 2; int c = (i & 3) * 8;       \
            cpa16(sA_ + r * 40 + c, A + (size_t)(bm + r) * K + (kt) + c);     \
            cpa16(sB_ + r * 40 + c, W + (size_t)(bn + r) * K + (kt) + c);     \
        }                                                                     \
        CP_COMMIT();                                                          \
    } while (0)

    GFILL(0, 0);
    int buf = 0;
    for (int kt = 0; kt < K; kt += 32) {
        if (kt + 32 < K) { GFILL(buf ^ 1, kt + 32); CP_WAIT(1); }
        else             { CP_WAIT(0); }
        __syncthreads();
        const __nv_bfloat16* sA = smh + buf * 10240;
        const __nv_bfloat16* sB = sA + 5120;
        #pragma unroll
        for (int ks = 0; ks < 2; ks++) {
            const int k0 = ks * 16 + 2 * t;
            uint32_t a[4][4], b[4][2];
            #pragma unroll
            for (int mf = 0; mf < 4; mf++) {
                const __nv_bfloat16* ap = sA + (wm * 64 + mf * 16 + g) * 40 + k0;
                a[mf][0] = *(const uint32_t*)ap;
                a[mf][1] = *(const uint32_t*)(ap + 8 * 40);
                a[mf][2] = *(const uint32_t*)(ap + 8);
                a[mf][3] = *(const uint32_t*)(ap + 8 * 40 + 8);
            }
            #pragma unroll
            for (int nf = 0; nf < 4; nf++) {
                const __nv_bfloat16* bp = sB + (wn * 32 + nf * 8 + g) * 40 + k0;
                b[nf][0] = *(const uint32_t*)bp;
                b[nf][1] = *(const uint32_t*)(bp + 8);
            }
            #pragma unroll
            for (int mf = 0; mf < 4; mf++)
                #pragma unroll
                for (int nf = 0; nf < 4; nf++)
                    mma16(acc[mf][nf], a[mf][0], a[mf][1], a[mf][2], a[mf][3],
                          b[nf][0], b[nf][1]);
        }
        __syncthreads();
        buf ^= 1;
    }
    #undef GFILL

    #pragma unroll
    for (int mf = 0; mf < 4; mf++) {
        #pragma unroll
        for (int nf = 0; nf < 4; nf++) {
            int row0 = bm + wm * 64 + mf * 16 + g;
            int col = bn + wn * 32 + nf * 8 + 2 * t;
            float2 bv = *(const float2*)&bias[col];
            #pragma unroll
            for (int h = 0; h < 2; h++) {
                int row = row0 + h * 8;
                float ox = acc[mf][nf][h * 2 + 0] + bv.x;
                float oy = acc[mf][nf][h * 2 + 1] + bv.y;
                if (EPI == 1) { ox = gelu_exact(ox); oy = gelu_exact(oy); }
                if (EPI == 2) {
                    float2 r2 = *(const float2*)(res + (size_t)row * N + col);
                    float2 o = make_float2(ox + r2.x, oy + r2.y);
                    *(float2*)((float*)Cv + (size_t)row * N + col) = o;
                } else {
                    *(uint32_t*)((__nv_bfloat16*)Cv + (size_t)row * N + col) =
                        bf2u(__floats2bfloat162_rn(ox, oy));
                }
            }
        }
    }
}

template <int EPI>
__global__ void __launch_bounds__(256, 2)
gemm_bf16(const __nv_bfloat16* __restrict__ A, const __nv_bfloat16* __restrict__ W,
          const float* __restrict__ bias, const float* __restrict__ res,
          void* __restrict__ Cv, int N, int K) {
    gemm_body<EPI>(A, W, bias, res, Cv, N, K);
}

__global__ void __launch_bounds__(256, 2)
gemm_qkv(const __nv_bfloat16* __restrict__ A, const __nv_bfloat16* __restrict__ wb,
         const float* __restrict__ bq, const float* __restrict__ bk,
         const float* __restrict__ bv,
         __nv_bfloat16* __restrict__ q, __nv_bfloat16* __restrict__ k,
         __nv_bfloat16* __restrict__ v) {
    int z = blockIdx.z;
    const __nv_bfloat16* W = wb + (size_t)z * 65536;
    const float* bias = (z == 0) ? bq : ((z == 1) ? bk : bv);
    __nv_bfloat16* C = (z == 0) ? q : ((z == 1) ? k : v);
    gemm_body<0>(A, W, bias, nullptr, C, 256, 256);
}

// ---------------- flash attention, bf16 mma, 110KB smem (2 CTA/SM) ---------
#define QKVS 264          // smem row stride in halves (528B, 16 mod 128 banks)
#define PSH  72

__global__ void __launch_bounds__(256, 2)
flash_tc(const __nv_bfloat16* __restrict__ Q, const __nv_bfloat16* __restrict__ Kg,
         const __nv_bfloat16* __restrict__ Vg, __nv_bfloat16* __restrict__ O) {
    extern __shared__ __align__(16) __nv_bfloat16 smh[];
    __nv_bfloat16* sQ = smh;                 // 64 x 264
    __nv_bfloat16* sK = sQ + 64 * QKVS;      // 64 x 264 (reused as O staging)
    __nv_bfloat16* sV = sK + 64 * QKVS;      // 64 x 264
    __nv_bfloat16* sP = sV + 64 * QKVS;      // 64 x 72
    __shared__ float sM[64], sL[64], sSc[64], sRmax[128], sRsum[128];

    const int tid = threadIdx.x, lane = tid & 31, wid = tid >> 5;
    const int wm = wid >> 1, wn = wid & 1;
    const int g = lane >> 2, t = lane & 3;

    // qblk schedule: co-resident pairs (id, id+148) sum to ~const work
    int id = blockIdx.x;
    int b = id & 3;
    int idx = id >> 2;
    int qblk = (idx < 32) ? (63 - 2 * idx) : (2 * (idx - 32));

    const size_t qbase = ((size_t)b * TT + (size_t)qblk * 64) * D;
    const size_t bbase = (size_t)b * TT * D;

    // prologue: Q + K(0), one group
    #pragma unroll
    for (int p = 0; p < 8; p++) {
        int i = tid + p * 256;
        int row = i >> 5, cv = i & 31;
        cpa16(sQ + row * QKVS + cv * 8, Q + qbase + (size_t)row * D + cv * 8);
        cpa16(sK + row * QKVS + cv * 8, Kg + bbase + (size_t)row * D + cv * 8);
    }
    CP_COMMIT();

    if (tid < 64) { sM[tid] = -1e30f; sL[tid] = 0.f; }

    float oacc[4][4][4];
    #pragma unroll
    for (int mf = 0; mf < 4; mf++)
        #pragma unroll
        for (int nf = 0; nf < 4; nf++)
            #pragma unroll
            for (int q = 0; q < 4; q++) oacc[mf][nf][q] = 0.f;

    const int rA = wm * 16 + g, rB = rA + 8;
    const int vro = ((lane >> 4) & 1) * 8 + (lane & 7);   // ldmatrix.trans row
    const int vco = ((lane >> 3) & 1) * 8;                // ldmatrix.trans col

    for (int j = 0; j <= qblk; j++) {
        __syncthreads();                                  // A: sV free
        {   // issue V(j)
            const __nv_bfloat16* vsrc = Vg + bbase + (size_t)j * 64 * D;
            #pragma unroll
            for (int p = 0; p < 8; p++) {
                int i = tid + p * 256;
                int row = i >> 5, cv = i & 31;
                cpa16(sV + row * QKVS + cv * 8, vsrc + (size_t)row * D + cv * 8);
            }
            CP_COMMIT();
        }
        CP_WAIT(1);                                       // K(j) (and Q) ready
        __syncthreads();                                  // B

        // ---- S = Q K^T ----
        float s4[4][4];
        #pragma unroll
        for (int nf = 0; nf < 4; nf++)
            #pragma unroll
            for (int q = 0; q < 4; q++) s4[nf][q] = 0.f;

        const __nv_bfloat16* qA = sQ + rA * QKVS;
        const __nv_bfloat16* qB = sQ + rB * QKVS;
        #pragma unroll 4
        for (int ks = 0; ks < 16; ks++) {
            const int k0 = ks * 16 + 2 * t;
            uint32_t a0 = *(const uint32_t*)(qA + k0);
            uint32_t a1 = *(const uint32_t*)(qB + k0);
            uint32_t a2 = *(const uint32_t*)(qA + k0 + 8);
            uint32_t a3 = *(const uint32_t*)(qB + k0 + 8);
            #pragma unroll
            for (int nf = 0; nf < 4; nf++) {
                const __nv_bfloat16* kp = sK + (wn * 32 + nf * 8 + g) * QKVS + k0;
                uint32_t b0 = *(const uint32_t*)kp;
                uint32_t b1 = *(const uint32_t*)(kp + 8);
                mma16(s4[nf], a0, a1, a2, a3, b0, b1);
            }
        }
        #pragma unroll
        for (int nf = 0; nf < 4; nf++)
            #pragma unroll
            for (int q = 0; q < 4; q++) s4[nf][q] *= 0.0625f;

        if (j == qblk) {                                  // causal mask
            #pragma unroll
            for (int nf = 0; nf < 4; nf++) {
                int c0 = wn * 32 + nf * 8 + 2 * t;
                if (c0 > rA)     s4[nf][0] = -1e30f;
                if (c0 + 1 > rA) s4[nf][1] = -1e30f;
                if (c0 > rB)     s4[nf][2] = -1e30f;
                if (c0 + 1 > rB) s4[nf][3] = -1e30f;
            }
        }

        // ---- row max ----
        float mA = -1e30f, mB = -1e30f;
        #pragma unroll
        for (int nf = 0; nf < 4; nf++) {
            mA = fmaxf(mA, fmaxf(s4[nf][0], s4[nf][1]));
            mB = fmaxf(mB, fmaxf(s4[nf][2], s4[nf][3]));
        }
        mA = fmaxf(mA, __shfl_xor_sync(0xffffffffu, mA, 1));
        mA = fmaxf(mA, __shfl_xor_sync(0xffffffffu, mA, 2));
        mB = fmaxf(mB, __shfl_xor_sync(0xffffffffu, mB, 1));
        mB = fmaxf(mB, __shfl_xor_sync(0xffffffffu, mB, 2));
        if (t == 0) { sRmax[wn * 64 + rA] = mA; sRmax[wn * 64 + rB] = mB; }
        __syncthreads();                                  // C: K reads done
        if (tid < 64) {
            float bmx = fmaxf(sRmax[tid], sRmax[64 + tid]);
            float nm = fmaxf(sM[tid], bmx);
            sSc[tid] = __expf(sM[tid] - nm);
            sM[tid] = nm;
        }
        // prefetch K(j+1) under softmax + PV
        if (j < qblk) {
            const __nv_bfloat16* ksrc = Kg + bbase + (size_t)(j + 1) * 64 * D;
            #pragma unroll
            for (int p = 0; p < 8; p++) {
                int i = tid + p * 256;
                int row = i >> 5, cv = i & 31;
                cpa16(sK + row * QKVS + cv * 8, ksrc + (size_t)row * D + cv * 8);
            }
            CP_COMMIT();
        }
        __syncthreads();                                  // D

        const float nmA = sM[rA], nmB = sM[rB];
        float sumA = 0.f, sumB = 0.f;
        #pragma unroll
        for (int nf = 0; nf < 4; nf++) {
            int c0 = wn * 32 + nf * 8 + 2 * t;
            float p0 = __expf(s4[nf][0] - nmA);
            float p1 = __expf(s4[nf][1] - nmA);
            float p2 = __expf(s4[nf][2] - nmB);
            float p3 = __expf(s4[nf][3] - nmB);
            sumA += p0 + p1; sumB += p2 + p3;
            *(uint32_t*)(sP + rA * PSH + c0) = bf2u(__floats2bfloat162_rn(p0, p1));
            *(uint32_t*)(sP + rB * PSH + c0) = bf2u(__floats2bfloat162_rn(p2, p3));
        }
        sumA += __shfl_xor_sync(0xffffffffu, sumA, 1);
        sumA += __shfl_xor_sync(0xffffffffu, sumA, 2);
        sumB += __shfl_xor_sync(0xffffffffu, sumB, 1);
        sumB += __shfl_xor_sync(0xffffffffu, sumB, 2);
        if (t == 0) { sRsum[wn * 64 + rA] = sumA; sRsum[wn * 64 + rB] = sumB; }

        if (j < qblk) CP_WAIT(1); else CP_WAIT(0);        // V(j) ready
        __syncthreads();                                  // E
        if (tid < 64) sL[tid] = sL[tid] * sSc[tid] + sRsum[tid] + sRsum[64 + tid];

        // rescale O accumulators
        #pragma unroll
        for (int nf = 0; nf < 4; nf++) {
            int qc = wn * 32 + nf * 8 + 2 * t;
            float sc0 = sSc[qc], sc1 = sSc[qc + 1];
            #pragma unroll
            for (int mf = 0; mf < 4; mf++) {
                oacc[mf][nf][0] *= sc0; oacc[mf][nf][1] *= sc1;
                oacc[mf][nf][2] *= sc0; oacc[mf][nf][3] *= sc1;
            }
        }

        // ---- O^T += V^T P^T (warp: 64 d-rows x 32 q-cols) ----
        #pragma unroll
        for (int ks = 0; ks < 4; ks++) {
            const int s0 = ks * 16;
            uint32_t bfr[4][2];
            #pragma unroll
            for (int nf = 0; nf < 4; nf++) {
                const __nv_bfloat16* pp = sP + (wn * 32 + nf * 8 + g) * PSH + s0 + 2 * t;
                bfr[nf][0] = *(const uint32_t*)pp;
                bfr[nf][1] = *(const uint32_t*)(pp + 8);
            }
            #pragma unroll
            for (int mf = 0; mf < 4; mf++) {
                uint32_t a0, a1, a2, a3;
                uint32_t addr = (uint32_t)__cvta_generic_to_shared(
                    sV + (s0 + vro) * QKVS + wm * 64 + mf * 16 + vco);
                asm volatile(
                    "ldmatrix.sync.aligned.m8n8.x4.trans.shared.b16 "
                    "{%0,%1,%2,%3}, [%4];"
                    : "=r"(a0), "=r"(a1), "=r"(a2), "=r"(a3) : "r"(addr));
                #pragma unroll
                for (int nf = 0; nf < 4; nf++)
                    mma16(oacc[mf][nf], a0, a1, a2, a3, bfr[nf][0], bfr[nf][1]);
            }
        }
    }

    __syncthreads();   // sL final, sK dead -> O staging
    __nv_bfloat16* sO = sK;
    #pragma unroll
    for (int nf = 0; nf < 4; nf++) {
        int qc = wn * 32 + nf * 8 + 2 * t;
        float inv0 = 1.0f / sL[qc], inv1 = 1.0f / sL[qc + 1];
        #pragma unroll
        for (int mf = 0; mf < 4; mf++) {
            int dl = wm * 64 + mf * 16 + g;
            sO[qc * QKVS + dl]           = __float2bfloat16(oacc[mf][nf][0] * inv0);
            sO[(qc + 1) * QKVS + dl]     = __float2bfloat16(oacc[mf][nf][1] * inv1);
            sO[qc * QKVS + dl + 8]       = __float2bfloat16(oacc[mf][nf][2] * inv0);
            sO[(qc + 1) * QKVS + dl + 8] = __float2bfloat16(oacc[mf][nf][3] * inv1);
        }
    }
    __syncthreads();
    #pragma unroll
    for (int p = 0; p < 8; p++) {
        int i = tid + p * 256;
        int row = i >> 5, cv = i & 31;
        *(uint4*)(O + qbase + (size_t)row * D + cv * 8) =
            *(const uint4*)(sO + row * QKVS + cv * 8);
    }
}

// ---------------- launch ----------------
extern "C" void kernel_launch(void* const* d_in, const int* in_sizes, int n_in,
                              void* d_out, int out_size) {
    const float* x   = (const float*)d_in[0];
    const float* anw = (const float*)d_in[1];
    const float* mnw = (const float*)d_in[2];
    const float* wq  = (const float*)d_in[3];
    const float* bq  = (const float*)d_in[4];
    const float* wk  = (const float*)d_in[5];
    const float* bk  = (const float*)d_in[6];
    const float* wv  = (const float*)d_in[7];
    const float* bv  = (const float*)d_in[8];
    const float* wo  = (const float*)d_in[9];
    const float* bo  = (const float*)d_in[10];
    const float* w1  = (const float*)d_in[11];
    const float* b1  = (const float*)d_in[12];
    const float* w2  = (const float*)d_in[13];
    const float* b2  = (const float*)d_in[14];
    float* out = (float*)d_out;

    __nv_bfloat16 *xn, *q, *k, *v, *attn, *hn, *h, *wb;
    cudaGetSymbolAddress((void**)&xn,   g_xnb);
    cudaGetSymbolAddress((void**)&q,    g_qb);
    cudaGetSymbolAddress((void**)&k,    g_kb);
    cudaGetSymbolAddress((void**)&v,    g_vb);
    cudaGetSymbolAddress((void**)&attn, g_attnb);
    cudaGetSymbolAddress((void**)&hn,   g_hnb);
    cudaGetSymbolAddress((void**)&h,    g_hb);
    cudaGetSymbolAddress((void**)&wb,   g_wb);

    const int GEMM_SMEM  = 2 * 2 * 128 * 40 * 2;                 // 40960
    const int FLASH_SMEM = (3 * 64 * QKVS + 64 * PSH) * 2;       // 110592
    cudaFuncSetAttribute(flash_tc, cudaFuncAttributeMaxDynamicSharedMemorySize, FLASH_SMEM);

    // 0) round weights to bf16
    convert_w<<<768, 256>>>(wq, wk, wv, wo, w1, w2, wb);
    // 1) attn-norm -> bf16
    rmsnorm_kernel<<<BT / 8, 256>>>(x, anw, xn);
    // 2) fused q,k,v projections
    gemm_qkv<<<dim3(2, 128, 3), 256, GEMM_SMEM>>>(xn, wb, bq, bk, bv, q, k, v);
    // 3) causal attention
    flash_tc<<<256, 256, FLASH_SMEM>>>(q, k, v, attn);
    // 4) output projection + residual (fp32 out)
    gemm_bf16<2><<<dim3(2, 128), 256, GEMM_SMEM>>>(attn, wb + 196608, bo, x, out, 256, 256);
    // 5) mlp-norm -> bf16
    rmsnorm_kernel<<<BT / 8, 256>>>(out, mnw, hn);
    // 6) mlp up + gelu -> bf16
    gemm_bf16<1><<<dim3(8, 128), 256, GEMM_SMEM>>>(hn, wb + 262144, b1, nullptr, h, 1024, 256);
    // 7) mlp down + residual (in-place on out)
    gemm_bf16<2><<<dim3(2, 128), 256, GEMM_SMEM>>>(h, wb + 524288, b2, out, out, 256, 1024);
}